// round 2
// baseline (speedup 1.0000x reference)
#include <cuda_runtime.h>
#include <cstdint>

// CRF log-partition forward scan.
// B=64 batches, L=512 max steps, C=1, N=128 tags.
// One block per batch (64 blocks x 128 threads). Thread j owns output tag j.
// exp(transitions) column j lives in 64 packed f32x2 registers per thread.
// Per step: p[i]=exp(alpha[i]-m) shared-broadcast, s[j]=sum_i p[i]*expT[i][j]
// via fma.rn.f32x2, alpha'[j]=log(s)+e_t[j] (relative to running offset m).
// Exact block-max renormalization every 4 steps only (drift bound << exp range).
// Emissions prefetched 2 steps ahead into rotating registers.

static constexpr int Bb = 64;
static constexpr int Ll = 512;
static constexpr int Nn = 128;

__device__ __forceinline__ unsigned long long fma2(unsigned long long a,
                                                   unsigned long long b,
                                                   unsigned long long c) {
    unsigned long long d;
    asm("fma.rn.f32x2 %0, %1, %2, %3;" : "=l"(d) : "l"(a), "l"(b), "l"(c));
    return d;
}
__device__ __forceinline__ unsigned long long add2(unsigned long long a,
                                                   unsigned long long b) {
    unsigned long long d;
    asm("add.rn.f32x2 %0, %1, %2;" : "=l"(d) : "l"(a), "l"(b));
    return d;
}
__device__ __forceinline__ unsigned long long pack2(float lo, float hi) {
    unsigned long long d;
    asm("mov.b64 %0, {%1, %2};" : "=l"(d) : "f"(lo), "f"(hi));
    return d;
}
__device__ __forceinline__ float lo2(unsigned long long v) {
    return __uint_as_float((unsigned)(v & 0xffffffffull));
}
__device__ __forceinline__ float hi2(unsigned long long v) {
    return __uint_as_float((unsigned)(v >> 32));
}

__global__ __launch_bounds__(128, 1)
void crf_forward_kernel(const float* __restrict__ emissions,
                        const float* __restrict__ transitions,
                        const float* __restrict__ start_t,
                        const float* __restrict__ end_t,
                        const int*   __restrict__ lengths,
                        float*       __restrict__ out)
{
    const int b    = blockIdx.x;
    const int j    = threadIdx.x;
    const int lane = j & 31;
    const int wid  = j >> 5;

    __shared__ __align__(16) float pbuf[2][Nn];
    __shared__ float red[4];

    const float* E = emissions + (size_t)b * Ll * Nn;

    // expT column j, packed as (expT[2m][j], expT[2m+1][j]) in 64 u64 regs.
    unsigned long long regT[64];
#pragma unroll
    for (int mI = 0; mI < 64; ++mI) {
        float lo = __expf(transitions[(2 * mI + 0) * Nn + j]);
        float hi = __expf(transitions[(2 * mI + 1) * Nn + j]);
        regT[mI] = pack2(lo, hi);
    }

    const int len  = lengths[b];
    const int last = len - 1;   // update steps are t = 1..last

    float a    = start_t[j] + E[j];  // alpha_0 (relative offset moff = 0)
    float moff = 0.0f;

    // rotating depth-2 emission prefetch
    float e0 = (1 <= last) ? E[1 * Nn + j] : 0.0f;
    float e1 = (2 <= last) ? E[2 * Nn + j] : 0.0f;

    for (int t = 1; t <= last; ++t) {
        float e2 = (t + 2 <= last) ? E[(t + 2) * Nn + j] : 0.0f;

        const int buf = t & 1;
        pbuf[buf][j] = __expf(a);
        __syncthreads();

        const ulonglong2* P = reinterpret_cast<const ulonglong2*>(pbuf[buf]);
        unsigned long long acc0 = 0ull, acc1 = 0ull, acc2 = 0ull, acc3 = 0ull;
#pragma unroll
        for (int k = 0; k < 32; k += 2) {
            ulonglong2 q = P[k];
            ulonglong2 r = P[k + 1];
            acc0 = fma2(q.x, regT[2 * k + 0], acc0);
            acc1 = fma2(q.y, regT[2 * k + 1], acc1);
            acc2 = fma2(r.x, regT[2 * k + 2], acc2);
            acc3 = fma2(r.y, regT[2 * k + 3], acc3);
        }
        acc0 = add2(acc0, acc1);
        acc2 = add2(acc2, acc3);
        acc0 = add2(acc0, acc2);
        float s = lo2(acc0) + hi2(acc0);

        a  = __logf(s) + e0;
        e0 = e1; e1 = e2;

        // lazy renormalization: exact block max every 4 steps.
        // per-step drift <= log(128)+max|T|+max e ~ 10, so 4-step drift << 88
        // (fp32 exp overflow), and never underflows to s == 0.
        if ((t & 3) == 0) {
            float v = a;
#pragma unroll
            for (int off = 16; off > 0; off >>= 1)
                v = fmaxf(v, __shfl_xor_sync(0xffffffffu, v, off));
            if (lane == 0) red[wid] = v;
            __syncthreads();
            float M = fmaxf(fmaxf(red[0], red[1]), fmaxf(red[2], red[3]));
            __syncthreads();
            a    -= M;
            moff += M;
        }
    }

    // out[b] = logsumexp_j(a[j] + end[j]) + moff
    float v = a + end_t[j];
    float w = v;
#pragma unroll
    for (int off = 16; off > 0; off >>= 1)
        w = fmaxf(w, __shfl_xor_sync(0xffffffffu, w, off));
    if (lane == 0) red[wid] = w;
    __syncthreads();
    float M2 = fmaxf(fmaxf(red[0], red[1]), fmaxf(red[2], red[3]));
    __syncthreads();

    float ex = __expf(v - M2);
#pragma unroll
    for (int off = 16; off > 0; off >>= 1)
        ex += __shfl_xor_sync(0xffffffffu, ex, off);
    if (lane == 0) red[wid] = ex;
    __syncthreads();

    if (j == 0) {
        float ssum = red[0] + red[1] + red[2] + red[3];
        out[b] = __logf(ssum) + M2 + moff;
    }
}

extern "C" void kernel_launch(void* const* d_in, const int* in_sizes, int n_in,
                              void* d_out, int out_size) {
    const float* emissions   = (const float*)d_in[0];
    const float* transitions = (const float*)d_in[1];
    const float* start_t     = (const float*)d_in[2];
    const float* end_t       = (const float*)d_in[3];
    const int*   lengths     = (const int*)  d_in[4];
    crf_forward_kernel<<<Bb, Nn>>>(emissions, transitions, start_t, end_t,
                                   lengths, (float*)d_out);
}

// round 3
// speedup vs baseline: 1.1617x; 1.1617x over previous
#include <cuda_runtime.h>
#include <cstdint>

// CRF log-partition forward scan, linear-domain formulation.
// B=64 batches, L=512 steps, C=1, N=128 tags. One block per batch,
// 128 threads, thread j owns tag j. exp(transitions) column j lives in
// 64 packed f32x2 registers.
//
// Recurrence kept in the exp domain:
//   u_t[j] = (sum_i u_{t-1}[i] * expT[i][j]) * exp(e_t[j]),  alpha = log u + C
// so NO exp/log sits on the per-step critical chain. exp(e_t) is produced by
// a depth-4 prefetch pipeline. Renormalization every 4 steps uses a sampled
// max of the shared u-buffer (broadcast LDS + fmax tree + rcp), overlapped
// with the fma2 dot product; C += log(M) accumulates off-chain.

static constexpr int Bb = 64;
static constexpr int Ll = 512;
static constexpr int Nn = 128;

__device__ __forceinline__ unsigned long long fma2(unsigned long long a,
                                                   unsigned long long b,
                                                   unsigned long long c) {
    unsigned long long d;
    asm("fma.rn.f32x2 %0, %1, %2, %3;" : "=l"(d) : "l"(a), "l"(b), "l"(c));
    return d;
}
__device__ __forceinline__ unsigned long long add2(unsigned long long a,
                                                   unsigned long long b) {
    unsigned long long d;
    asm("add.rn.f32x2 %0, %1, %2;" : "=l"(d) : "l"(a), "l"(b));
    return d;
}
__device__ __forceinline__ unsigned long long pack2(float lo, float hi) {
    unsigned long long d;
    asm("mov.b64 %0, {%1, %2};" : "=l"(d) : "f"(lo), "f"(hi));
    return d;
}
__device__ __forceinline__ float lo2(unsigned long long v) {
    return __uint_as_float((unsigned)(v & 0xffffffffull));
}
__device__ __forceinline__ float hi2(unsigned long long v) {
    return __uint_as_float((unsigned)(v >> 32));
}

__global__ __launch_bounds__(128, 1)
void crf_forward_kernel(const float* __restrict__ emissions,
                        const float* __restrict__ transitions,
                        const float* __restrict__ start_t,
                        const float* __restrict__ end_t,
                        const int*   __restrict__ lengths,
                        float*       __restrict__ out)
{
    const int b    = blockIdx.x;
    const int j    = threadIdx.x;
    const int lane = j & 31;
    const int wid  = j >> 5;

    __shared__ __align__(16) float pbuf[2][Nn];
    __shared__ float red[4];

    const float* E = emissions + (size_t)b * Ll * Nn;

    // expT column j, packed (expT[2m][j], expT[2m+1][j]) in 64 u64 regs.
    unsigned long long regT[64];
#pragma unroll
    for (int mI = 0; mI < 64; ++mI) {
        float lo = __expf(transitions[(2 * mI + 0) * Nn + j]);
        float hi = __expf(transitions[(2 * mI + 1) * Nn + j]);
        regT[mI] = pack2(lo, hi);
    }

    const int len  = lengths[b];
    const int last = len - 1;   // update steps t = 1..last

    float u = __expf(start_t[j] + E[j]);   // u_0 = exp(alpha_0), C = 0
    float C = 0.0f;
    const float pend = __expf(end_t[j]);

    // emission prefetch pipeline (clamped indices keep loads in bounds;
    // over-read values are never used because the loop ends first)
    auto eld = [&](int t) -> float {
        int tt = t > last ? last : t;
        if (tt < 1) tt = 1;
        return E[(size_t)tt * Nn + j];
    };
    float pe_use = 1.0f, pe_nxt = 1.0f, raw2 = 0.0f, raw3 = 0.0f;
    if (last >= 1) {
        pe_use = __expf(eld(1));
        pe_nxt = __expf(eld(2));
        raw2   = eld(3);
        raw3   = eld(4);
    }

    for (int t = 1; t <= last; ++t) {
        const int buf = t & 1;
        pbuf[buf][j] = u;
        __syncthreads();

        // renormalization scale from sampled max of u_{t-1} (broadcast LDS,
        // identical on all threads -> uniform, deterministic scaling)
        const bool rn = ((t & 3) == 0);
        float rscale = 1.0f;
        if (rn) {
            float sm[16];
#pragma unroll
            for (int q = 0; q < 16; ++q) sm[q] = pbuf[buf][q * 8];
#pragma unroll
            for (int st = 8; st > 0; st >>= 1)
#pragma unroll
                for (int q = 0; q < 8; ++q)
                    if (q < st) sm[q] = fmaxf(sm[q], sm[q + st]);
            const float M = sm[0];
            rscale = __fdividef(1.0f, M);
            C += __logf(M);
        }

        // s[j] = sum_i u_{t-1}[i] * expT[i][j]
        const ulonglong2* P = reinterpret_cast<const ulonglong2*>(pbuf[buf]);
        unsigned long long acc0 = 0ull, acc1 = 0ull, acc2 = 0ull, acc3 = 0ull;
#pragma unroll
        for (int k = 0; k < 32; k += 2) {
            ulonglong2 q = P[k];
            ulonglong2 r = P[k + 1];
            acc0 = fma2(q.x, regT[2 * k + 0], acc0);
            acc1 = fma2(q.y, regT[2 * k + 1], acc1);
            acc2 = fma2(r.x, regT[2 * k + 2], acc2);
            acc3 = fma2(r.y, regT[2 * k + 3], acc3);
        }
        acc0 = add2(acc0, acc1);
        acc2 = add2(acc2, acc3);
        acc0 = add2(acc0, acc2);
        const float s = lo2(acc0) + hi2(acc0);

        u = s * (pe_use * rscale);          // u_t (rscale folded off-chain)

        // rotate prefetch pipeline (all off the critical chain)
        const float pe_new  = __expf(raw2); // exp for step t+2
        const float raw_new = eld(t + 4);   // raw emission for step t+4
        pe_use = pe_nxt; pe_nxt = pe_new;
        raw2 = raw3;     raw3 = raw_new;
    }

    // out[b] = log( sum_j u[j] * exp(end[j]) ) + C
    float ex = u * pend;
#pragma unroll
    for (int off = 16; off > 0; off >>= 1)
        ex += __shfl_xor_sync(0xffffffffu, ex, off);
    if (lane == 0) red[wid] = ex;
    __syncthreads();

    if (j == 0) {
        float ssum = red[0] + red[1] + red[2] + red[3];
        out[b] = __logf(ssum) + C;
    }
}

extern "C" void kernel_launch(void* const* d_in, const int* in_sizes, int n_in,
                              void* d_out, int out_size) {
    const float* emissions   = (const float*)d_in[0];
    const float* transitions = (const float*)d_in[1];
    const float* start_t     = (const float*)d_in[2];
    const float* end_t       = (const float*)d_in[3];
    const int*   lengths     = (const int*)  d_in[4];
    crf_forward_kernel<<<Bb, Nn>>>(emissions, transitions, start_t, end_t,
                                   lengths, (float*)d_out);
}